// round 16
// baseline (speedup 1.0000x reference)
#include <cuda_runtime.h>
#include <cuda_bf16.h>
#include <math.h>
#include <stdint.h>

#define B_ 8
#define N_ 2048
#define D_ 1024
#define H_ 512

// ---------------- scratch (device globals; no allocations allowed) ----------
__device__ float         g_xn [(size_t)B_ * N_ * D_];   // normalized x (fp32, exact rescore)
__device__ __nv_bfloat16 g_xnh[(size_t)B_ * N_ * D_];   // bf16(xn) for approx S
__device__ float2        g_candv[(size_t)B_ * N_ * 16 * 8]; // per-(row,tile) top-8 (val,idx)
__device__ __nv_bfloat16 g_hh [(size_t)B_ * N_ * D_];   // h = x+agg, split
__device__ __nv_bfloat16 g_hl [(size_t)B_ * N_ * D_];
__device__ __nv_bfloat16 g_h1h[(size_t)B_ * N_ * H_];   // relu(h W1 + b1), split
__device__ __nv_bfloat16 g_h1l[(size_t)B_ * N_ * H_];
__device__ __nv_bfloat16 g_w1th[(size_t)H_ * D_];       // W1^T split  [512,1024]
__device__ __nv_bfloat16 g_w1tl[(size_t)H_ * D_];
__device__ __nv_bfloat16 g_w2th[(size_t)H_ * H_];       // W2^T split  [512,512]
__device__ __nv_bfloat16 g_w2tl[(size_t)H_ * H_];
__device__ int           g_cand[(size_t)B_ * N_ * 8];   // merged top-8 candidates
__device__ int           g_idx5[(size_t)B_ * N_ * 5];
__device__ float         g_w5 [(size_t)B_ * N_ * 5];

// ---------------- helpers ----------------------------------------------------
__device__ __forceinline__ uint32_t smem_u32(const void* p) {
    uint32_t a;
    asm("{ .reg .u64 t; cvta.to.shared.u64 t, %1; cvt.u32.u64 %0, t; }" : "=r"(a) : "l"(p));
    return a;
}
__device__ __forceinline__ void cp16(uint32_t s, const void* g) {
    asm volatile("cp.async.cg.shared.global [%0], [%1], 16;" :: "r"(s), "l"(g));
}
__device__ __forceinline__ void cp_commit() { asm volatile("cp.async.commit_group;"); }
template <int NN> __device__ __forceinline__ void cp_wait() {
    asm volatile("cp.async.wait_group %0;" :: "n"(NN));
}
__device__ __forceinline__ void ldsm4(uint32_t* r, uint32_t addr) {
    asm volatile("ldmatrix.sync.aligned.m8n8.x4.shared.b16 {%0,%1,%2,%3}, [%4];"
                 : "=r"(r[0]), "=r"(r[1]), "=r"(r[2]), "=r"(r[3]) : "r"(addr));
}
__device__ __forceinline__ void mma16816(float* d, const uint32_t* a, const uint32_t* b) {
    asm volatile("mma.sync.aligned.m16n8k16.row.col.f32.bf16.bf16.f32 "
                 "{%0,%1,%2,%3}, {%4,%5,%6,%7}, {%8,%9}, {%0,%1,%2,%3};"
                 : "+f"(d[0]), "+f"(d[1]), "+f"(d[2]), "+f"(d[3])
                 : "r"(a[0]), "r"(a[1]), "r"(a[2]), "r"(a[3]), "r"(b[0]), "r"(b[1]));
}

// ---------------- kernel 1: row-normalize + bf16 hi --------------------------
__global__ void norm_kernel(const float* __restrict__ x, float* __restrict__ xn,
                            __nv_bfloat16* __restrict__ xnh) {
    int row = blockIdx.x;
    const float4* xr = (const float4*)(x + (size_t)row * D_);
    int t = threadIdx.x;
    float4 v = xr[t];
    float ss = v.x * v.x + v.y * v.y + v.z * v.z + v.w * v.w;
    #pragma unroll
    for (int o = 16; o; o >>= 1) ss += __shfl_xor_sync(0xffffffffu, ss, o);
    __shared__ float sred[8];
    if ((t & 31) == 0) sred[t >> 5] = ss;
    __syncthreads();
    if (t < 8) {
        float s = sred[t];
        #pragma unroll
        for (int o = 4; o; o >>= 1) s += __shfl_xor_sync(0xffu, s, o);
        if (t == 0) sred[0] = 1.0f / (sqrtf(s) + 1e-8f);
    }
    __syncthreads();
    float inv = sred[0];
    v.x *= inv; v.y *= inv; v.z *= inv; v.w *= inv;
    ((float4*)(xn + (size_t)row * D_))[t] = v;

    __nv_bfloat162* ph = (__nv_bfloat162*)(xnh + (size_t)row * D_ + t * 4);
    ph[0] = __nv_bfloat162(__float2bfloat16(v.x), __float2bfloat16(v.y));
    ph[1] = __nv_bfloat162(__float2bfloat16(v.z), __float2bfloat16(v.w));
}

// ---------------- kernel 2: weight transpose + split -------------------------
__global__ void wtrans_kernel(const float* __restrict__ W, __nv_bfloat16* __restrict__ Th,
                              __nv_bfloat16* __restrict__ Tl, int K) {
    __shared__ float t[32][33];
    int k0 = blockIdx.x * 32, n0 = blockIdx.y * 32;
    int tx = threadIdx.x, ty = threadIdx.y;        // 32 x 8
    for (int i = ty; i < 32; i += 8) t[i][tx] = W[(size_t)(k0 + i) * H_ + n0 + tx];
    __syncthreads();
    for (int i = ty; i < 32; i += 8) {
        float v = t[tx][i];                        // = W[k0+tx][n0+i]
        __nv_bfloat16 h = __float2bfloat16(v);
        __nv_bfloat16 l = __float2bfloat16(v - __bfloat162float(h));
        size_t o = (size_t)(n0 + i) * K + k0 + tx;
        Th[o] = h; Tl[o] = l;
    }
}

// ---------------- GEMM tiling constants --------------------------------------
#define KC 64
#define LDSB 72                        // bf16 per smem row (64 + 8 pad)
#define TILE_B (128 * LDSB * 2)        // 18432 bytes per tile

// ---------------- S GEMM fused with per-tile top-8 extraction ----------------
// 128 threads, 4 warps of 64x64 tiles (8 ldsm : 32 mma per k16 step -> 33%
// less LDSM traffic per MMA than 64x32). 2 CTAs/SM. Epilogue: stage tile,
// vectorized float4 top-8 scan (direct rows), then re-stage transposed and
// scan mirror rows the same way. Only 8 (val,idx) pairs per row reach HBM.
#define S_STAGE (2 * TILE_B)           // A, B = 36864
#define S_SMEM  (2 * S_STAGE)          // 73728
__global__ void __launch_bounds__(128, 2) gemm_s(const __nv_bfloat16* __restrict__ Xh,
                                                 float2* __restrict__ candv) {
    extern __shared__ char dsm[];
    uint32_t sb = smem_u32(dsm);
    int tid = threadIdx.x, wid = tid >> 5, lane = tid & 31;
    int wr = wid >> 1, wc = wid & 1;              // warp tile: 64 x 64

    int b = blockIdx.y;
    int rem = blockIdx.x, tm = 0;
    while (rem >= 16 - tm) { rem -= 16 - tm; tm++; }
    int tn = tm + rem;
    int rowBase = tm * 128, colBase = tn * 128;
    const __nv_bfloat16* Ag = Xh + ((size_t)b * N_ + rowBase) * D_;
    const __nv_bfloat16* Bg = Xh + ((size_t)b * N_ + colBase) * D_;

    float acc[4][8][4];
    #pragma unroll
    for (int i = 0; i < 4; i++)
        #pragma unroll
        for (int j = 0; j < 8; j++)
            #pragma unroll
            for (int e = 0; e < 4; e++) acc[i][j][e] = 0.0f;

    const int NC = D_ / KC;               // 16
    auto load_stage = [&](int c, int s) {
        uint32_t base = sb + s * S_STAGE;
        #pragma unroll
        for (int i = 0; i < 16; i++) {
            int li = tid + i * 128;               // 0..2047
            int m = li >> 10;                     // tile select
            int r = (li >> 3) & 127;
            int seg = li & 7;
            const __nv_bfloat16* gp = (m ? Bg : Ag) + c * KC;
            cp16(base + (uint32_t)(m * TILE_B + r * (LDSB * 2) + seg * 16),
                 gp + (size_t)r * D_ + seg * 8);
        }
        cp_commit();
    };
    load_stage(0, 0);

    int arow = lane & 15;
    int akk  = ((lane >> 4) & 1) * 8;
    int brow = (lane & 7) + ((lane >> 4) & 1) * 8;
    int bkk  = ((lane >> 3) & 1) * 8;

    for (int c = 0; c < NC; c++) {
        int s = c & 1;
        cp_wait<0>();                     // own copies of chunk c landed
        __syncthreads();                  // publish to all threads
        if (c + 1 < NC) load_stage(c + 1, s ^ 1);   // overlaps compute below

        uint32_t tA = sb + s * S_STAGE, tB = tA + TILE_B;
        #pragma unroll
        for (int ks = 0; ks < 4; ks++) {
            uint32_t a_off = (uint32_t)((wr * 64 + arow) * (LDSB * 2) + (ks * 16 + akk) * 2);
            uint32_t b_off = (uint32_t)((wc * 64 + brow) * (LDSB * 2) + (ks * 16 + bkk) * 2);
            uint32_t a[4][4], bfr[4][4];
            #pragma unroll
            for (int nb = 0; nb < 4; nb++)
                ldsm4(bfr[nb], tB + b_off + (uint32_t)(nb * 16 * (LDSB * 2)));
            #pragma unroll
            for (int mi = 0; mi < 4; mi++)
                ldsm4(a[mi], tA + a_off + (uint32_t)(mi * 16 * (LDSB * 2)));
            #pragma unroll
            for (int mi = 0; mi < 4; mi++)
                #pragma unroll
                for (int ni = 0; ni < 8; ni++)
                    mma16816(acc[mi][ni], a[mi], &bfr[ni >> 1][(ni & 1) * 2]);
        }
        __syncthreads();                  // all warps done reading stage s
    }

    // ---- epilogue 1: stage tile (direct orientation) ------------------------
    float (*st)[132] = (float (*)[132])dsm;
    int g = lane >> 2, tg = lane & 3;
    #pragma unroll
    for (int mi = 0; mi < 4; mi++) {
        #pragma unroll
        for (int ni = 0; ni < 8; ni++) {
            float* d = acc[mi][ni];
            int lr = wr * 64 + mi * 16 + g;
            int lc = wc * 64 + ni * 8 + tg * 2;
            st[lr][lc]         = d[0];
            st[lr][lc + 1]     = d[1];
            st[lr + 8][lc]     = d[2];
            st[lr + 8][lc + 1] = d[3];
        }
    }
    __syncthreads();

    const float NEG = __int_as_float(0xff800000);

    // ---- direct scan: row rowBase+tid over cols colBase+j -------------------
    {
        int lr = tid;
        float v[8]; int ixr[8];
        #pragma unroll
        for (int j = 0; j < 8; j++) { v[j] = NEG; ixr[j] = -1; }
        int diagGroup = (tm == tn) ? (lr & ~3) : -1;
        for (int j0 = 0; j0 < 128; j0 += 4) {
            float4 q = *(const float4*)&st[lr][j0];
            float vmax = fmaxf(fmaxf(q.x, q.y), fmaxf(q.z, q.w));
            if (j0 == diagGroup || vmax > v[7]) {
                #pragma unroll
                for (int e = 0; e < 4; e++) {
                    int j = j0 + e;
                    if (tm == tn && j == lr) continue;
                    float xv = ((const float*)&q)[e];
                    if (xv > v[7]) {
                        v[7] = xv; ixr[7] = colBase + j;
                        #pragma unroll
                        for (int q2 = 6; q2 >= 0; q2--) {
                            if (v[q2 + 1] > v[q2]) {
                                float tv = v[q2]; v[q2] = v[q2 + 1]; v[q2 + 1] = tv;
                                int ti = ixr[q2]; ixr[q2] = ixr[q2 + 1]; ixr[q2 + 1] = ti;
                            }
                        }
                    }
                }
            }
        }
        float2* dst = candv + (((size_t)(b * N_ + rowBase + lr)) * 16 + tn) * 8;
        #pragma unroll
        for (int j = 0; j < 8; j++)
            dst[j] = make_float2(v[j], __int_as_float(ixr[j]));
    }

    // ---- mirror: re-stage transposed, scan rows -----------------------------
    if (tm != tn) {
        __syncthreads();
        #pragma unroll
        for (int mi = 0; mi < 4; mi++) {
            #pragma unroll
            for (int ni = 0; ni < 8; ni++) {
                float* d = acc[mi][ni];
                int r0 = wr * 64 + mi * 16 + g;
                int c0 = wc * 64 + ni * 8 + tg * 2;
                st[c0][r0]         = d[0];
                st[c0 + 1][r0]     = d[1];
                st[c0][r0 + 8]     = d[2];
                st[c0 + 1][r0 + 8] = d[3];
            }
        }
        __syncthreads();

        int lc = tid;
        float v[8]; int ixr[8];
        #pragma unroll
        for (int j = 0; j < 8; j++) { v[j] = NEG; ixr[j] = -1; }
        for (int j0 = 0; j0 < 128; j0 += 4) {
            float4 q = *(const float4*)&st[lc][j0];
            float vmax = fmaxf(fmaxf(q.x, q.y), fmaxf(q.z, q.w));
            if (vmax > v[7]) {
                #pragma unroll
                for (int e = 0; e < 4; e++) {
                    float xv = ((const float*)&q)[e];
                    if (xv > v[7]) {
                        v[7] = xv; ixr[7] = rowBase + j0 + e;
                        #pragma unroll
                        for (int q2 = 6; q2 >= 0; q2--) {
                            if (v[q2 + 1] > v[q2]) {
                                float tv = v[q2]; v[q2] = v[q2 + 1]; v[q2 + 1] = tv;
                                int ti = ixr[q2]; ixr[q2] = ixr[q2 + 1]; ixr[q2 + 1] = ti;
                            }
                        }
                    }
                }
            }
        }
        float2* dst = candv + (((size_t)(b * N_ + colBase + lc)) * 16 + tm) * 8;
        #pragma unroll
        for (int j = 0; j < 8; j++)
            dst[j] = make_float2(v[j], __int_as_float(ixr[j]));
    }
}

// ---------------- kernel 3a: merge 16x8 per-tile candidates -> global top-8 --
__global__ void merge8_kernel(const float2* __restrict__ candv, int* __restrict__ candO) {
    int warp = threadIdx.x >> 5, lane = threadIdx.x & 31;
    int row = blockIdx.x * 8 + warp;
    const float2* cv = candv + (size_t)row * 128;
    const float NEG = __int_as_float(0xff800000);

    float v[8]; int ix[8];
    #pragma unroll
    for (int j = 0; j < 8; j++) { v[j] = NEG; ix[j] = -1; }
    #pragma unroll
    for (int k = 0; k < 4; k++) {
        float2 e = cv[lane * 4 + k];
        float xv = e.x;
        if (xv > v[7]) {
            v[7] = xv; ix[7] = __float_as_int(e.y);
            #pragma unroll
            for (int q = 6; q >= 0; q--) {
                if (v[q + 1] > v[q]) {
                    float tv = v[q]; v[q] = v[q + 1]; v[q + 1] = tv;
                    int ti = ix[q]; ix[q] = ix[q + 1]; ix[q + 1] = ti;
                }
            }
        }
    }
    #pragma unroll
    for (int off = 16; off; off >>= 1) {
        float ov[8]; int oix[8];
        #pragma unroll
        for (int j = 0; j < 8; j++) {
            ov[j]  = __shfl_xor_sync(0xffffffffu, v[j],  off);
            oix[j] = __shfl_xor_sync(0xffffffffu, ix[j], off);
        }
        float nv[8]; int nix[8];
        int p = 0, q = 0;
        #pragma unroll
        for (int j = 0; j < 8; j++) {
            if (v[p] >= ov[q]) { nv[j] = v[p]; nix[j] = ix[p]; p++; }
            else               { nv[j] = ov[q]; nix[j] = oix[q]; q++; }
        }
        #pragma unroll
        for (int j = 0; j < 8; j++) { v[j] = nv[j]; ix[j] = nix[j]; }
    }
    if (lane == 0) {
        #pragma unroll
        for (int j = 0; j < 8; j++)
            candO[(size_t)row * 8 + j] = ix[j];
    }
}

// ---------------- kernel 3b: bit-exact sequential fp32 rescore + top5 --------
__global__ void __launch_bounds__(256) rescore_kernel(const float* __restrict__ xn,
                                                      const int* __restrict__ cand,
                                                      int* __restrict__ idxO,
                                                      float* __restrict__ wO) {
    __shared__ float s_ev[256];
    __shared__ int   s_ec[256];
    int tid = threadIdx.x;
    int row = blockIdx.x * 32 + (tid >> 3);
    int slot = tid & 7;
    int b = row >> 11, n = row & (N_ - 1);
    int c = cand[(size_t)row * 8 + slot];

    const float4* xr = (const float4*)(xn + ((size_t)b * N_ + n) * D_);
    const float4* xc = (const float4*)(xn + ((size_t)b * N_ + c) * D_);
    float p = 0.0f;
    #pragma unroll 8
    for (int i = 0; i < D_ / 4; i++) {
        float4 a = xr[i], q = xc[i];
        p = fmaf(a.x, q.x, p);
        p = fmaf(a.y, q.y, p);
        p = fmaf(a.z, q.z, p);
        p = fmaf(a.w, q.w, p);
    }
    s_ev[tid] = p;
    s_ec[tid] = c;
    __syncthreads();

    if (slot == 0) {
        float ev[8]; int ec[8]; bool used[8];
        #pragma unroll
        for (int j = 0; j < 8; j++) {
            ev[j] = s_ev[tid + j];
            ec[j] = s_ec[tid + j];
            used[j] = false;
        }
        float selv[5]; int seli[5];
        #pragma unroll
        for (int s = 0; s < 5; s++) {
            int best = -1;
            #pragma unroll
            for (int j = 0; j < 8; j++) {
                if (used[j]) continue;
                if (best < 0 || ev[j] > ev[best] ||
                    (ev[j] == ev[best] && ec[j] < ec[best])) best = j;
            }
            used[best] = true;
            selv[s] = ev[best]; seli[s] = ec[best];
        }
        float m = selv[0], ssum = 0.0f, e[5];
        #pragma unroll
        for (int j = 0; j < 5; j++) { e[j] = expf(selv[j] - m); ssum += e[j]; }
        float invs = 1.0f / ssum;
        #pragma unroll
        for (int j = 0; j < 5; j++) {
            wO[(size_t)row * 5 + j]   = e[j] * invs;
            idxO[(size_t)row * 5 + j] = seli[j];
        }
    }
}

// ---------------- kernel 4: h = x + sum_j w_j * x[idx_j], bf16 split ---------
__global__ void agg_kernel(const float* __restrict__ x, const int* __restrict__ idx,
                           const float* __restrict__ w, __nv_bfloat16* __restrict__ hh,
                           __nv_bfloat16* __restrict__ hl) {
    int row = blockIdx.x;
    int b = row >> 11;
    int n = row & (N_ - 1);
    const float* xb = x + ((size_t)b * N_) * D_;

    int   i0 = idx[(size_t)row * 5 + 0], i1 = idx[(size_t)row * 5 + 1],
          i2 = idx[(size_t)row * 5 + 2], i3 = idx[(size_t)row * 5 + 3],
          i4 = idx[(size_t)row * 5 + 4];
    float w0 = w[(size_t)row * 5 + 0], w1 = w[(size_t)row * 5 + 1],
          w2 = w[(size_t)row * 5 + 2], w3 = w[(size_t)row * 5 + 3],
          w4 = w[(size_t)row * 5 + 4];

    int d = threadIdx.x << 2;
    float4 r  = *(const float4*)(xb + (size_t)n  * D_ + d);
    float4 a0 = *(const float4*)(xb + (size_t)i0 * D_ + d);
    float4 a1 = *(const float4*)(xb + (size_t)i1 * D_ + d);
    float4 a2 = *(const float4*)(xb + (size_t)i2 * D_ + d);
    float4 a3 = *(const float4*)(xb + (size_t)i3 * D_ + d);
    float4 a4 = *(const float4*)(xb + (size_t)i4 * D_ + d);
    r.x += w0 * a0.x + w1 * a1.x + w2 * a2.x + w3 * a3.x + w4 * a4.x;
    r.y += w0 * a0.y + w1 * a1.y + w2 * a2.y + w3 * a3.y + w4 * a4.y;
    r.z += w0 * a0.z + w1 * a1.z + w2 * a2.z + w3 * a3.z + w4 * a4.z;
    r.w += w0 * a0.w + w1 * a1.w + w2 * a2.w + w3 * a3.w + w4 * a4.w;

    __nv_bfloat16 h0 = __float2bfloat16(r.x), h1 = __float2bfloat16(r.y);
    __nv_bfloat16 h2 = __float2bfloat16(r.z), h3 = __float2bfloat16(r.w);
    __nv_bfloat16 l0 = __float2bfloat16(r.x - __bfloat162float(h0));
    __nv_bfloat16 l1 = __float2bfloat16(r.y - __bfloat162float(h1));
    __nv_bfloat16 l2 = __float2bfloat16(r.z - __bfloat162float(h2));
    __nv_bfloat16 l3 = __float2bfloat16(r.w - __bfloat162float(h3));
    __nv_bfloat162* ph = (__nv_bfloat162*)(hh + (size_t)row * D_ + d);
    __nv_bfloat162* pl = (__nv_bfloat162*)(hl + (size_t)row * D_ + d);
    ph[0] = __nv_bfloat162(h0, h1); ph[1] = __nv_bfloat162(h2, h3);
    pl[0] = __nv_bfloat162(l0, l1); pl[1] = __nv_bfloat162(l2, l3);
}

// ---------------- split-bf16 MLP GEMM via mma.sync: D = A * B^T --------------
// MODE 1: layer 1 (bias+relu, write bf16 hi/lo); MODE 2: layer 2 (write fp32)
#define MLP_STAGE (4 * TILE_B)         // Ah, Al, Bh, Bl = 73728
#define MLP_SMEM  (2 * MLP_STAGE)      // 147456

template <int MODE>
__global__ void __launch_bounds__(256) gemm_split(
    const __nv_bfloat16* __restrict__ Ah, const __nv_bfloat16* __restrict__ Al,
    const __nv_bfloat16* __restrict__ Bh, const __nv_bfloat16* __restrict__ Bl,
    const float* __restrict__ bias,
    float* __restrict__ Cf, __nv_bfloat16* __restrict__ Ch, __nv_bfloat16* __restrict__ Cl,
    int K) {
    extern __shared__ char dsm[];
    uint32_t sb = smem_u32(dsm);
    int tid = threadIdx.x, wid = tid >> 5, lane = tid & 31;
    int wr = wid >> 2, wc = wid & 3;

    int rowBase = blockIdx.y * 128, colBase = blockIdx.x * 128;
    size_t aOff = (size_t)rowBase * K;
    size_t bOff = (size_t)colBase * K;
    const __nv_bfloat16* mats[4] = { Ah + aOff, Al + aOff, Bh + bOff, Bl + bOff };

    float acc[4][4][4];
    #pragma unroll
    for (int i = 0; i < 4; i++)
        #pragma unroll
        for (int j = 0; j < 4; j++)
            #pragma unroll
            for (int e = 0; e < 4; e++) acc[i][j][e] = 0.0f;

    const int NC = K / KC;
    auto load_stage = [&](int c, int s) {
        uint32_t base = sb + s * MLP_STAGE;
        #pragma unroll
        for (int m = 0; m < 4; m++) {
            const __nv_bfloat16* gp = mats[m] + c * KC;
            uint32_t tb = base + m * TILE_B;
            #pragma unroll
            for (int i = 0; i < 4; i++) {
                int li = tid + i * 256;
                int row = li >> 3, seg = li & 7;
                cp16(tb + (uint32_t)(row * (LDSB * 2) + seg * 16),
                     gp + (size_t)row * K + seg * 8);
            }
        }
        cp_commit();
    };
    load_stage(0, 0);

    int arow = lane & 15;
    int akk  = ((lane >> 4) & 1) * 8;
    int brow = (lane & 7) + ((lane >> 4) & 1) * 8;
    int bkk  = ((lane >> 3) & 1) * 8;

    for (int c = 0; c < NC; c++) {
        int s = c & 1;
        cp_wait<0>();
        __syncthreads();
        if (c + 1 < NC) load_stage(c + 1, s ^ 1);

        uint32_t base = sb + s * MLP_STAGE;
        uint32_t tAh = base, tAl = base + TILE_B;
        uint32_t tBh = base + 2 * TILE_B, tBl = base + 3 * TILE_B;

        #pragma unroll
        for (int ks = 0; ks < 4; ks++) {
            uint32_t a_off = (uint32_t)((wr * 64 + arow) * (LDSB * 2) + (ks * 16 + akk) * 2);
            uint32_t b_off = (uint32_t)((wc * 32 + brow) * (LDSB * 2) + (ks * 16 + bkk) * 2);

            uint32_t ah[4][4], al[4][4], bh4[2][4], bl4[2][4];
            #pragma unroll
            for (int nb = 0; nb < 2; nb++) {
                ldsm4(bh4[nb], tBh + b_off + (uint32_t)(nb * 16 * (LDSB * 2)));
                ldsm4(bl4[nb], tBl + b_off + (uint32_t)(nb * 16 * (LDSB * 2)));
            }
            #pragma unroll
            for (int mi = 0; mi < 4; mi++)
                ldsm4(ah[mi], tAh + a_off + (uint32_t)(mi * 16 * (LDSB * 2)));
            #pragma unroll
            for (int mi = 0; mi < 4; mi++)
                ldsm4(al[mi], tAl + a_off + (uint32_t)(mi * 16 * (LDSB * 2)));

            #pragma unroll
            for (int mi = 0; mi < 4; mi++)
                #pragma unroll
                for (int ni = 0; ni < 4; ni++)
                    mma16816(acc[mi][ni], ah[mi], &bh4[ni >> 1][(ni & 1) * 2]);
            #pragma unroll
            for (int mi = 0; mi < 4; mi++)
                #pragma unroll
                for (int ni = 0; ni < 4; ni++)
                    mma16816(acc[mi][ni], ah[mi], &bl4[ni >> 1][(ni & 1) * 2]);
            #pragma unroll
            for (int mi = 0; mi < 4; mi++)
                #pragma unroll
                for (int ni = 0; ni < 4; ni++)
                    mma16816(acc[mi][ni], al[mi], &bh4[ni >> 1][(ni & 1) * 2]);
        }
        __syncthreads();
    }

    int g = lane >> 2, tg = lane & 3;
    int rb0 = rowBase + wr * 64;
    int cb0 = colBase + wc * 32;
    #pragma unroll
    for (int mi = 0; mi < 4; mi++) {
        #pragma unroll
        for (int ni = 0; ni < 4; ni++) {
            float* d = acc[mi][ni];
            int r0 = rb0 + mi * 16 + g;
            int c0 = cb0 + ni * 8 + tg * 2;
            float bv0 = bias[c0], bv1 = bias[c0 + 1];
            #pragma unroll
            for (int half = 0; half < 2; half++) {
                int r = r0 + half * 8;
                float v0 = fmaxf(d[half * 2 + 0] + bv0, 0.0f);
                float v1 = fmaxf(d[half * 2 + 1] + bv1, 0.0f);
                if (MODE == 1) {
                    __nv_bfloat16 h0 = __float2bfloat16(v0);
                    __nv_bfloat16 h1 = __float2bfloat16(v1);
                    __nv_bfloat16 l0 = __float2bfloat16(v0 - __bfloat162float(h0));
                    __nv_bfloat16 l1 = __float2bfloat16(v1 - __bfloat162float(h1));
                    size_t o = (size_t)r * H_ + c0;
                    *(__nv_bfloat162*)(Ch + o) = __nv_bfloat162(h0, h1);
                    *(__nv_bfloat162*)(Cl + o) = __nv_bfloat162(l0, l1);
                } else {
                    *(float2*)(Cf + (size_t)r * H_ + c0) = make_float2(v0, v1);
                }
            }
        }
    }
}

// ---------------- launcher ---------------------------------------------------
extern "C" void kernel_launch(void* const* d_in, const int* in_sizes, int n_in,
                              void* d_out, int out_size) {
    const float* x  = (const float*)d_in[0];
    const float* w1 = (const float*)d_in[1];
    const float* b1 = (const float*)d_in[2];
    const float* w2 = (const float*)d_in[3];
    const float* b2 = (const float*)d_in[4];
    float* out = (float*)d_out;

    float *xn, *w5; int *idx5, *cand; float2* candv;
    __nv_bfloat16 *xnh, *hh, *hl, *h1h, *h1l, *w1th, *w1tl, *w2th, *w2tl;
    cudaGetSymbolAddress((void**)&xn,    g_xn);
    cudaGetSymbolAddress((void**)&xnh,   g_xnh);
    cudaGetSymbolAddress((void**)&candv, g_candv);
    cudaGetSymbolAddress((void**)&hh,    g_hh);
    cudaGetSymbolAddress((void**)&hl,    g_hl);
    cudaGetSymbolAddress((void**)&h1h,   g_h1h);
    cudaGetSymbolAddress((void**)&h1l,   g_h1l);
    cudaGetSymbolAddress((void**)&w1th,  g_w1th);
    cudaGetSymbolAddress((void**)&w1tl,  g_w1tl);
    cudaGetSymbolAddress((void**)&w2th,  g_w2th);
    cudaGetSymbolAddress((void**)&w2tl,  g_w2tl);
    cudaGetSymbolAddress((void**)&cand,  g_cand);
    cudaGetSymbolAddress((void**)&idx5,  g_idx5);
    cudaGetSymbolAddress((void**)&w5,    g_w5);

    cudaFuncSetAttribute(gemm_s, cudaFuncAttributeMaxDynamicSharedMemorySize, S_SMEM);
    cudaFuncSetAttribute(gemm_split<1>, cudaFuncAttributeMaxDynamicSharedMemorySize, MLP_SMEM);
    cudaFuncSetAttribute(gemm_split<2>, cudaFuncAttributeMaxDynamicSharedMemorySize, MLP_SMEM);

    norm_kernel<<<B_ * N_, 256>>>(x, xn, xnh);

    dim3 wt1(D_ / 32, H_ / 32), wblk(32, 8);
    wtrans_kernel<<<wt1, wblk>>>(w1, w1th, w1tl, D_);
    dim3 wt2(H_ / 32, H_ / 32);
    wtrans_kernel<<<wt2, wblk>>>(w2, w2th, w2tl, H_);

    dim3 sg(136, B_);
    gemm_s<<<sg, 128, S_SMEM>>>(xnh, candv);

    merge8_kernel<<<(B_ * N_) / 8, 256>>>(candv, cand);

    rescore_kernel<<<(B_ * N_) / 32, 256>>>(xn, cand, idx5, w5);

    agg_kernel<<<B_ * N_, 256>>>(x, idx5, w5, hh, hl);

    dim3 g1(H_ / 128, (B_ * N_) / 128);
    gemm_split<1><<<g1, 256, MLP_SMEM>>>(hh, hl, w1th, w1tl, b1,
                                         nullptr, h1h, h1l, D_);
    gemm_split<2><<<g1, 256, MLP_SMEM>>>(h1h, h1l, w2th, w2tl, b2,
                                         out, nullptr, nullptr, H_);
}

// round 17
// speedup vs baseline: 1.0678x; 1.0678x over previous
#include <cuda_runtime.h>
#include <cuda_bf16.h>
#include <math.h>
#include <stdint.h>

#define B_ 8
#define N_ 2048
#define D_ 1024
#define H_ 512

// ---------------- scratch (device globals; no allocations allowed) ----------
__device__ float         g_xn [(size_t)B_ * N_ * D_];   // normalized x (fp32, exact rescore)
__device__ __nv_bfloat16 g_xnh[(size_t)B_ * N_ * D_];   // bf16(xn) for approx S
__device__ float2        g_candv[(size_t)B_ * N_ * 16 * 8]; // per-(row,tile) top-8 (val,idx)
__device__ __nv_bfloat16 g_hh [(size_t)B_ * N_ * D_];   // h = x+agg, split
__device__ __nv_bfloat16 g_hl [(size_t)B_ * N_ * D_];
__device__ __nv_bfloat16 g_h1h[(size_t)B_ * N_ * H_];   // relu(h W1 + b1), split
__device__ __nv_bfloat16 g_h1l[(size_t)B_ * N_ * H_];
__device__ __nv_bfloat16 g_w1th[(size_t)H_ * D_];       // W1^T split  [512,1024]
__device__ __nv_bfloat16 g_w1tl[(size_t)H_ * D_];
__device__ __nv_bfloat16 g_w2th[(size_t)H_ * H_];       // W2^T split  [512,512]
__device__ __nv_bfloat16 g_w2tl[(size_t)H_ * H_];
__device__ int           g_cand[(size_t)B_ * N_ * 8];   // merged top-8 candidates
__device__ int           g_idx5[(size_t)B_ * N_ * 5];
__device__ float         g_w5 [(size_t)B_ * N_ * 5];

// ---------------- helpers ----------------------------------------------------
__device__ __forceinline__ uint32_t smem_u32(const void* p) {
    uint32_t a;
    asm("{ .reg .u64 t; cvta.to.shared.u64 t, %1; cvt.u32.u64 %0, t; }" : "=r"(a) : "l"(p));
    return a;
}
__device__ __forceinline__ void cp16(uint32_t s, const void* g) {
    asm volatile("cp.async.cg.shared.global [%0], [%1], 16;" :: "r"(s), "l"(g));
}
__device__ __forceinline__ void cp_commit() { asm volatile("cp.async.commit_group;"); }
template <int NN> __device__ __forceinline__ void cp_wait() {
    asm volatile("cp.async.wait_group %0;" :: "n"(NN));
}
__device__ __forceinline__ void ldsm4(uint32_t* r, uint32_t addr) {
    asm volatile("ldmatrix.sync.aligned.m8n8.x4.shared.b16 {%0,%1,%2,%3}, [%4];"
                 : "=r"(r[0]), "=r"(r[1]), "=r"(r[2]), "=r"(r[3]) : "r"(addr));
}
__device__ __forceinline__ void mma16816(float* d, const uint32_t* a, const uint32_t* b) {
    asm volatile("mma.sync.aligned.m16n8k16.row.col.f32.bf16.bf16.f32 "
                 "{%0,%1,%2,%3}, {%4,%5,%6,%7}, {%8,%9}, {%0,%1,%2,%3};"
                 : "+f"(d[0]), "+f"(d[1]), "+f"(d[2]), "+f"(d[3])
                 : "r"(a[0]), "r"(a[1]), "r"(a[2]), "r"(a[3]), "r"(b[0]), "r"(b[1]));
}

// ---------------- kernel 1: row-normalize + bf16 hi --------------------------
__global__ void norm_kernel(const float* __restrict__ x, float* __restrict__ xn,
                            __nv_bfloat16* __restrict__ xnh) {
    int row = blockIdx.x;
    const float4* xr = (const float4*)(x + (size_t)row * D_);
    int t = threadIdx.x;
    float4 v = xr[t];
    float ss = v.x * v.x + v.y * v.y + v.z * v.z + v.w * v.w;
    #pragma unroll
    for (int o = 16; o; o >>= 1) ss += __shfl_xor_sync(0xffffffffu, ss, o);
    __shared__ float sred[8];
    if ((t & 31) == 0) sred[t >> 5] = ss;
    __syncthreads();
    if (t < 8) {
        float s = sred[t];
        #pragma unroll
        for (int o = 4; o; o >>= 1) s += __shfl_xor_sync(0xffu, s, o);
        if (t == 0) sred[0] = 1.0f / (sqrtf(s) + 1e-8f);
    }
    __syncthreads();
    float inv = sred[0];
    v.x *= inv; v.y *= inv; v.z *= inv; v.w *= inv;
    ((float4*)(xn + (size_t)row * D_))[t] = v;

    __nv_bfloat162* ph = (__nv_bfloat162*)(xnh + (size_t)row * D_ + t * 4);
    ph[0] = __nv_bfloat162(__float2bfloat16(v.x), __float2bfloat16(v.y));
    ph[1] = __nv_bfloat162(__float2bfloat16(v.z), __float2bfloat16(v.w));
}

// ---------------- kernel 2: weight transpose + split -------------------------
__global__ void wtrans_kernel(const float* __restrict__ W, __nv_bfloat16* __restrict__ Th,
                              __nv_bfloat16* __restrict__ Tl, int K) {
    __shared__ float t[32][33];
    int k0 = blockIdx.x * 32, n0 = blockIdx.y * 32;
    int tx = threadIdx.x, ty = threadIdx.y;        // 32 x 8
    for (int i = ty; i < 32; i += 8) t[i][tx] = W[(size_t)(k0 + i) * H_ + n0 + tx];
    __syncthreads();
    for (int i = ty; i < 32; i += 8) {
        float v = t[tx][i];                        // = W[k0+tx][n0+i]
        __nv_bfloat16 h = __float2bfloat16(v);
        __nv_bfloat16 l = __float2bfloat16(v - __bfloat162float(h));
        size_t o = (size_t)(n0 + i) * K + k0 + tx;
        Th[o] = h; Tl[o] = l;
    }
}

// ---------------- GEMM tiling constants --------------------------------------
#define KC 64
#define LDSB 72                        // bf16 per smem row (64 + 8 pad)
#define TILE_B (128 * LDSB * 2)        // 18432 bytes per tile

// ---------------- S GEMM fused with per-tile top-8 extraction ----------------
// Round-15 configuration (64x32 warp tiles, 256 threads, 2 CTAs/SM).
// Epilogue: stage tile in smem; direct scan is float4 + group-max skip
// (provably bit-identical top-8); mirror scan scalar over columns.
#define S_STAGE (2 * TILE_B)           // A, B = 36864
#define S_SMEM  (2 * S_STAGE)          // 73728
__global__ void __launch_bounds__(256, 2) gemm_s(const __nv_bfloat16* __restrict__ Xh,
                                                 float2* __restrict__ candv) {
    extern __shared__ char dsm[];
    uint32_t sb = smem_u32(dsm);
    int tid = threadIdx.x, wid = tid >> 5, lane = tid & 31;
    int wr = wid >> 2, wc = wid & 3;              // warp tile: 64 x 32

    int b = blockIdx.y;
    int rem = blockIdx.x, tm = 0;
    while (rem >= 16 - tm) { rem -= 16 - tm; tm++; }
    int tn = tm + rem;
    int rowBase = tm * 128, colBase = tn * 128;
    const __nv_bfloat16* Ag = Xh + ((size_t)b * N_ + rowBase) * D_;
    const __nv_bfloat16* Bg = Xh + ((size_t)b * N_ + colBase) * D_;

    float acc[4][4][4];
    #pragma unroll
    for (int i = 0; i < 4; i++)
        #pragma unroll
        for (int j = 0; j < 4; j++)
            #pragma unroll
            for (int e = 0; e < 4; e++) acc[i][j][e] = 0.0f;

    const int NC = D_ / KC;               // 16
    auto load_stage = [&](int c, int s) {
        uint32_t base = sb + s * S_STAGE;
        #pragma unroll
        for (int m = 0; m < 2; m++) {
            const __nv_bfloat16* gp = (m ? Bg : Ag) + c * KC;
            uint32_t tb = base + m * TILE_B;
            #pragma unroll
            for (int i = 0; i < 4; i++) {
                int li = tid + i * 256;
                int row = li >> 3, seg = li & 7;
                cp16(tb + (uint32_t)(row * (LDSB * 2) + seg * 16),
                     gp + (size_t)row * D_ + seg * 8);
            }
        }
        cp_commit();
    };
    load_stage(0, 0);

    int arow = lane & 15;
    int akk  = ((lane >> 4) & 1) * 8;
    int brow = (lane & 7) + ((lane >> 4) & 1) * 8;
    int bkk  = ((lane >> 3) & 1) * 8;

    uint32_t af[2][4][4], bf[2][2][4];    // double-buffered fragments

    for (int c = 0; c < NC; c++) {
        int s = c & 1;
        cp_wait<0>();                     // own copies of chunk c landed
        __syncthreads();                  // publish to all threads
        if (c + 1 < NC) load_stage(c + 1, s ^ 1);   // overlaps compute below

        uint32_t tA = sb + s * S_STAGE, tB = tA + TILE_B;
        {
            uint32_t a_off = (uint32_t)((wr * 64 + arow) * (LDSB * 2) + akk * 2);
            uint32_t b_off = (uint32_t)((wc * 32 + brow) * (LDSB * 2) + bkk * 2);
            ldsm4(bf[0][0], tB + b_off);
            ldsm4(bf[0][1], tB + b_off + (uint32_t)(16 * (LDSB * 2)));
            #pragma unroll
            for (int mi = 0; mi < 4; mi++)
                ldsm4(af[0][mi], tA + a_off + (uint32_t)(mi * 16 * (LDSB * 2)));
        }
        #pragma unroll
        for (int ks = 0; ks < 4; ks++) {
            int cur = ks & 1;
            if (ks < 3) {
                int nxt = cur ^ 1;
                uint32_t a_off = (uint32_t)((wr * 64 + arow) * (LDSB * 2) + ((ks + 1) * 16 + akk) * 2);
                uint32_t b_off = (uint32_t)((wc * 32 + brow) * (LDSB * 2) + ((ks + 1) * 16 + bkk) * 2);
                ldsm4(bf[nxt][0], tB + b_off);
                ldsm4(bf[nxt][1], tB + b_off + (uint32_t)(16 * (LDSB * 2)));
                #pragma unroll
                for (int mi = 0; mi < 4; mi++)
                    ldsm4(af[nxt][mi], tA + a_off + (uint32_t)(mi * 16 * (LDSB * 2)));
            }
            #pragma unroll
            for (int mi = 0; mi < 4; mi++)
                #pragma unroll
                for (int ni = 0; ni < 4; ni++)
                    mma16816(acc[mi][ni], af[cur][mi], &bf[cur][ni >> 1][(ni & 1) * 2]);
        }
        __syncthreads();                  // all warps done reading stage s
    }

    // ---- epilogue: stage 128x128 tile in smem -------------------------------
    float (*st)[132] = (float (*)[132])dsm;
    int g = lane >> 2, tg = lane & 3;
    #pragma unroll
    for (int mi = 0; mi < 4; mi++) {
        #pragma unroll
        for (int ni = 0; ni < 4; ni++) {
            float* d = acc[mi][ni];
            int lr = wr * 64 + mi * 16 + g;
            int lc = wc * 32 + ni * 8 + tg * 2;
            st[lr][lc]         = d[0];
            st[lr][lc + 1]     = d[1];
            st[lr + 8][lc]     = d[2];
            st[lr + 8][lc + 1] = d[3];
        }
    }
    __syncthreads();

    // ---- per-tile top-8 extraction ------------------------------------------
    const float NEG = __int_as_float(0xff800000);
    float v[8]; int ixr[8];
    #pragma unroll
    for (int j = 0; j < 8; j++) { v[j] = NEG; ixr[j] = -1; }

    if (tid < 128) {
        // direct: row rowBase+tid, candidates colBase+j (float4 + group skip)
        int lr = tid;
        for (int j0 = 0; j0 < 128; j0 += 4) {
            float4 q = *(const float4*)&st[lr][j0];
            float vmax = fmaxf(fmaxf(q.x, q.y), fmaxf(q.z, q.w));
            if (vmax > v[7]) {
                #pragma unroll
                for (int e = 0; e < 4; e++) {
                    int j = j0 + e;
                    if (tm == tn && j == lr) continue;     // diagonal
                    float xv = ((const float*)&q)[e];
                    if (xv > v[7]) {
                        v[7] = xv; ixr[7] = colBase + j;
                        #pragma unroll
                        for (int q2 = 6; q2 >= 0; q2--) {
                            if (v[q2 + 1] > v[q2]) {
                                float tv = v[q2]; v[q2] = v[q2 + 1]; v[q2 + 1] = tv;
                                int ti = ixr[q2]; ixr[q2] = ixr[q2 + 1]; ixr[q2 + 1] = ti;
                            }
                        }
                    }
                }
            }
        }
        float2* dst = candv + (((size_t)(b * N_ + rowBase + lr)) * 16 + tn) * 8;
        #pragma unroll
        for (int j = 0; j < 8; j++)
            dst[j] = make_float2(v[j], __int_as_float(ixr[j]));
    } else if (tm != tn) {
        // mirror: row colBase+lc, candidates rowBase+j (column scan, coalesced)
        int lc = tid - 128;
        for (int j = 0; j < 128; j++) {
            float xv = st[j][lc];
            if (xv > v[7]) {
                v[7] = xv; ixr[7] = rowBase + j;
                #pragma unroll
                for (int q = 6; q >= 0; q--) {
                    if (v[q + 1] > v[q]) {
                        float tv = v[q]; v[q] = v[q + 1]; v[q + 1] = tv;
                        int ti = ixr[q]; ixr[q] = ixr[q + 1]; ixr[q + 1] = ti;
                    }
                }
            }
        }
        float2* dst = candv + (((size_t)(b * N_ + colBase + lc)) * 16 + tm) * 8;
        #pragma unroll
        for (int j = 0; j < 8; j++)
            dst[j] = make_float2(v[j], __int_as_float(ixr[j]));
    }
}

// ---------------- kernel 3a: merge 16x8 per-tile candidates -> global top-8 --
__global__ void merge8_kernel(const float2* __restrict__ candv, int* __restrict__ candO) {
    int warp = threadIdx.x >> 5, lane = threadIdx.x & 31;
    int row = blockIdx.x * 8 + warp;
    const float2* cv = candv + (size_t)row * 128;
    const float NEG = __int_as_float(0xff800000);

    float v[8]; int ix[8];
    #pragma unroll
    for (int j = 0; j < 8; j++) { v[j] = NEG; ix[j] = -1; }
    #pragma unroll
    for (int k = 0; k < 4; k++) {
        float2 e = cv[lane * 4 + k];
        float xv = e.x;
        if (xv > v[7]) {
            v[7] = xv; ix[7] = __float_as_int(e.y);
            #pragma unroll
            for (int q = 6; q >= 0; q--) {
                if (v[q + 1] > v[q]) {
                    float tv = v[q]; v[q] = v[q + 1]; v[q + 1] = tv;
                    int ti = ix[q]; ix[q] = ix[q + 1]; ix[q + 1] = ti;
                }
            }
        }
    }
    #pragma unroll
    for (int off = 16; off; off >>= 1) {
        float ov[8]; int oix[8];
        #pragma unroll
        for (int j = 0; j < 8; j++) {
            ov[j]  = __shfl_xor_sync(0xffffffffu, v[j],  off);
            oix[j] = __shfl_xor_sync(0xffffffffu, ix[j], off);
        }
        float nv[8]; int nix[8];
        int p = 0, q = 0;
        #pragma unroll
        for (int j = 0; j < 8; j++) {
            if (v[p] >= ov[q]) { nv[j] = v[p]; nix[j] = ix[p]; p++; }
            else               { nv[j] = ov[q]; nix[j] = oix[q]; q++; }
        }
        #pragma unroll
        for (int j = 0; j < 8; j++) { v[j] = nv[j]; ix[j] = nix[j]; }
    }
    if (lane == 0) {
        #pragma unroll
        for (int j = 0; j < 8; j++)
            candO[(size_t)row * 8 + j] = ix[j];
    }
}

// ---------------- kernel 3b: bit-exact sequential fp32 rescore + top5 --------
__global__ void __launch_bounds__(256) rescore_kernel(const float* __restrict__ xn,
                                                      const int* __restrict__ cand,
                                                      int* __restrict__ idxO,
                                                      float* __restrict__ wO) {
    __shared__ float s_ev[256];
    __shared__ int   s_ec[256];
    int tid = threadIdx.x;
    int row = blockIdx.x * 32 + (tid >> 3);
    int slot = tid & 7;
    int b = row >> 11, n = row & (N_ - 1);
    int c = cand[(size_t)row * 8 + slot];

    const float4* xr = (const float4*)(xn + ((size_t)b * N_ + n) * D_);
    const float4* xc = (const float4*)(xn + ((size_t)b * N_ + c) * D_);
    float p = 0.0f;
    #pragma unroll 8
    for (int i = 0; i < D_ / 4; i++) {
        float4 a = xr[i], q = xc[i];
        p = fmaf(a.x, q.x, p);
        p = fmaf(a.y, q.y, p);
        p = fmaf(a.z, q.z, p);
        p = fmaf(a.w, q.w, p);
    }
    s_ev[tid] = p;
    s_ec[tid] = c;
    __syncthreads();

    if (slot == 0) {
        float ev[8]; int ec[8]; bool used[8];
        #pragma unroll
        for (int j = 0; j < 8; j++) {
            ev[j] = s_ev[tid + j];
            ec[j] = s_ec[tid + j];
            used[j] = false;
        }
        float selv[5]; int seli[5];
        #pragma unroll
        for (int s = 0; s < 5; s++) {
            int best = -1;
            #pragma unroll
            for (int j = 0; j < 8; j++) {
                if (used[j]) continue;
                if (best < 0 || ev[j] > ev[best] ||
                    (ev[j] == ev[best] && ec[j] < ec[best])) best = j;
            }
            used[best] = true;
            selv[s] = ev[best]; seli[s] = ec[best];
        }
        float m = selv[0], ssum = 0.0f, e[5];
        #pragma unroll
        for (int j = 0; j < 5; j++) { e[j] = expf(selv[j] - m); ssum += e[j]; }
        float invs = 1.0f / ssum;
        #pragma unroll
        for (int j = 0; j < 5; j++) {
            wO[(size_t)row * 5 + j]   = e[j] * invs;
            idxO[(size_t)row * 5 + j] = seli[j];
        }
    }
}

// ---------------- kernel 4: h = x + sum_j w_j * x[idx_j], bf16 split ---------
__global__ void agg_kernel(const float* __restrict__ x, const int* __restrict__ idx,
                           const float* __restrict__ w, __nv_bfloat16* __restrict__ hh,
                           __nv_bfloat16* __restrict__ hl) {
    int row = blockIdx.x;
    int b = row >> 11;
    int n = row & (N_ - 1);
    const float* xb = x + ((size_t)b * N_) * D_;

    int   i0 = idx[(size_t)row * 5 + 0], i1 = idx[(size_t)row * 5 + 1],
          i2 = idx[(size_t)row * 5 + 2], i3 = idx[(size_t)row * 5 + 3],
          i4 = idx[(size_t)row * 5 + 4];
    float w0 = w[(size_t)row * 5 + 0], w1 = w[(size_t)row * 5 + 1],
          w2 = w[(size_t)row * 5 + 2], w3 = w[(size_t)row * 5 + 3],
          w4 = w[(size_t)row * 5 + 4];

    int d = threadIdx.x << 2;
    float4 r  = *(const float4*)(xb + (size_t)n  * D_ + d);
    float4 a0 = *(const float4*)(xb + (size_t)i0 * D_ + d);
    float4 a1 = *(const float4*)(xb + (size_t)i1 * D_ + d);
    float4 a2 = *(const float4*)(xb + (size_t)i2 * D_ + d);
    float4 a3 = *(const float4*)(xb + (size_t)i3 * D_ + d);
    float4 a4 = *(const float4*)(xb + (size_t)i4 * D_ + d);
    r.x += w0 * a0.x + w1 * a1.x + w2 * a2.x + w3 * a3.x + w4 * a4.x;
    r.y += w0 * a0.y + w1 * a1.y + w2 * a2.y + w3 * a3.y + w4 * a4.y;
    r.z += w0 * a0.z + w1 * a1.z + w2 * a2.z + w3 * a3.z + w4 * a4.z;
    r.w += w0 * a0.w + w1 * a1.w + w2 * a2.w + w3 * a3.w + w4 * a4.w;

    __nv_bfloat16 h0 = __float2bfloat16(r.x), h1 = __float2bfloat16(r.y);
    __nv_bfloat16 h2 = __float2bfloat16(r.z), h3 = __float2bfloat16(r.w);
    __nv_bfloat16 l0 = __float2bfloat16(r.x - __bfloat162float(h0));
    __nv_bfloat16 l1 = __float2bfloat16(r.y - __bfloat162float(h1));
    __nv_bfloat16 l2 = __float2bfloat16(r.z - __bfloat162float(h2));
    __nv_bfloat16 l3 = __float2bfloat16(r.w - __bfloat162float(h3));
    __nv_bfloat162* ph = (__nv_bfloat162*)(hh + (size_t)row * D_ + d);
    __nv_bfloat162* pl = (__nv_bfloat162*)(hl + (size_t)row * D_ + d);
    ph[0] = __nv_bfloat162(h0, h1); ph[1] = __nv_bfloat162(h2, h3);
    pl[0] = __nv_bfloat162(l0, l1); pl[1] = __nv_bfloat162(l2, l3);
}

// ---------------- split-bf16 MLP GEMM via mma.sync: D = A * B^T --------------
// MODE 1: layer 1 (bias+relu, write bf16 hi/lo); MODE 2: layer 2 (write fp32)
#define MLP_STAGE (4 * TILE_B)         // Ah, Al, Bh, Bl = 73728
#define MLP_SMEM  (2 * MLP_STAGE)      // 147456

template <int MODE>
__global__ void __launch_bounds__(256) gemm_split(
    const __nv_bfloat16* __restrict__ Ah, const __nv_bfloat16* __restrict__ Al,
    const __nv_bfloat16* __restrict__ Bh, const __nv_bfloat16* __restrict__ Bl,
    const float* __restrict__ bias,
    float* __restrict__ Cf, __nv_bfloat16* __restrict__ Ch, __nv_bfloat16* __restrict__ Cl,
    int K) {
    extern __shared__ char dsm[];
    uint32_t sb = smem_u32(dsm);
    int tid = threadIdx.x, wid = tid >> 5, lane = tid & 31;
    int wr = wid >> 2, wc = wid & 3;

    int rowBase = blockIdx.y * 128, colBase = blockIdx.x * 128;
    size_t aOff = (size_t)rowBase * K;
    size_t bOff = (size_t)colBase * K;
    const __nv_bfloat16* mats[4] = { Ah + aOff, Al + aOff, Bh + bOff, Bl + bOff };

    float acc[4][4][4];
    #pragma unroll
    for (int i = 0; i < 4; i++)
        #pragma unroll
        for (int j = 0; j < 4; j++)
            #pragma unroll
            for (int e = 0; e < 4; e++) acc[i][j][e] = 0.0f;

    const int NC = K / KC;
    auto load_stage = [&](int c, int s) {
        uint32_t base = sb + s * MLP_STAGE;
        #pragma unroll
        for (int m = 0; m < 4; m++) {
            const __nv_bfloat16* gp = mats[m] + c * KC;
            uint32_t tb = base + m * TILE_B;
            #pragma unroll
            for (int i = 0; i < 4; i++) {
                int li = tid + i * 256;
                int row = li >> 3, seg = li & 7;
                cp16(tb + (uint32_t)(row * (LDSB * 2) + seg * 16),
                     gp + (size_t)row * K + seg * 8);
            }
        }
        cp_commit();
    };
    load_stage(0, 0);

    int arow = lane & 15;
    int akk  = ((lane >> 4) & 1) * 8;
    int brow = (lane & 7) + ((lane >> 4) & 1) * 8;
    int bkk  = ((lane >> 3) & 1) * 8;

    for (int c = 0; c < NC; c++) {
        int s = c & 1;
        cp_wait<0>();
        __syncthreads();
        if (c + 1 < NC) load_stage(c + 1, s ^ 1);

        uint32_t base = sb + s * MLP_STAGE;
        uint32_t tAh = base, tAl = base + TILE_B;
        uint32_t tBh = base + 2 * TILE_B, tBl = base + 3 * TILE_B;

        #pragma unroll
        for (int ks = 0; ks < 4; ks++) {
            uint32_t a_off = (uint32_t)((wr * 64 + arow) * (LDSB * 2) + (ks * 16 + akk) * 2);
            uint32_t b_off = (uint32_t)((wc * 32 + brow) * (LDSB * 2) + (ks * 16 + bkk) * 2);

            uint32_t ah[4][4], al[4][4], bh4[2][4], bl4[2][4];
            #pragma unroll
            for (int nb = 0; nb < 2; nb++) {
                ldsm4(bh4[nb], tBh + b_off + (uint32_t)(nb * 16 * (LDSB * 2)));
                ldsm4(bl4[nb], tBl + b_off + (uint32_t)(nb * 16 * (LDSB * 2)));
            }
            #pragma unroll
            for (int mi = 0; mi < 4; mi++)
                ldsm4(ah[mi], tAh + a_off + (uint32_t)(mi * 16 * (LDSB * 2)));
            #pragma unroll
            for (int mi = 0; mi < 4; mi++)
                ldsm4(al[mi], tAl + a_off + (uint32_t)(mi * 16 * (LDSB * 2)));

            #pragma unroll
            for (int mi = 0; mi < 4; mi++)
                #pragma unroll
                for (int ni = 0; ni < 4; ni++)
                    mma16816(acc[mi][ni], ah[mi], &bh4[ni >> 1][(ni & 1) * 2]);
            #pragma unroll
            for (int mi = 0; mi < 4; mi++)
                #pragma unroll
                for (int ni = 0; ni < 4; ni++)
                    mma16816(acc[mi][ni], ah[mi], &bl4[ni >> 1][(ni & 1) * 2]);
            #pragma unroll
            for (int mi = 0; mi < 4; mi++)
                #pragma unroll
                for (int ni = 0; ni < 4; ni++)
                    mma16816(acc[mi][ni], al[mi], &bh4[ni >> 1][(ni & 1) * 2]);
        }
        __syncthreads();
    }

    int g = lane >> 2, tg = lane & 3;
    int rb0 = rowBase + wr * 64;
    int cb0 = colBase + wc * 32;
    #pragma unroll
    for (int mi = 0; mi < 4; mi++) {
        #pragma unroll
        for (int ni = 0; ni < 4; ni++) {
            float* d = acc[mi][ni];
            int r0 = rb0 + mi * 16 + g;
            int c0 = cb0 + ni * 8 + tg * 2;
            float bv0 = bias[c0], bv1 = bias[c0 + 1];
            #pragma unroll
            for (int half = 0; half < 2; half++) {
                int r = r0 + half * 8;
                float v0 = fmaxf(d[half * 2 + 0] + bv0, 0.0f);
                float v1 = fmaxf(d[half * 2 + 1] + bv1, 0.0f);
                if (MODE == 1) {
                    __nv_bfloat16 h0 = __float2bfloat16(v0);
                    __nv_bfloat16 h1 = __float2bfloat16(v1);
                    __nv_bfloat16 l0 = __float2bfloat16(v0 - __bfloat162float(h0));
                    __nv_bfloat16 l1 = __float2bfloat16(v1 - __bfloat162float(h1));
                    size_t o = (size_t)r * H_ + c0;
                    *(__nv_bfloat162*)(Ch + o) = __nv_bfloat162(h0, h1);
                    *(__nv_bfloat162*)(Cl + o) = __nv_bfloat162(l0, l1);
                } else {
                    *(float2*)(Cf + (size_t)r * H_ + c0) = make_float2(v0, v1);
                }
            }
        }
    }
}

// ---------------- launcher ---------------------------------------------------
extern "C" void kernel_launch(void* const* d_in, const int* in_sizes, int n_in,
                              void* d_out, int out_size) {
    const float* x  = (const float*)d_in[0];
    const float* w1 = (const float*)d_in[1];
    const float* b1 = (const float*)d_in[2];
    const float* w2 = (const float*)d_in[3];
    const float* b2 = (const float*)d_in[4];
    float* out = (float*)d_out;

    float *xn, *w5; int *idx5, *cand; float2* candv;
    __nv_bfloat16 *xnh, *hh, *hl, *h1h, *h1l, *w1th, *w1tl, *w2th, *w2tl;
    cudaGetSymbolAddress((void**)&xn,    g_xn);
    cudaGetSymbolAddress((void**)&xnh,   g_xnh);
    cudaGetSymbolAddress((void**)&candv, g_candv);
    cudaGetSymbolAddress((void**)&hh,    g_hh);
    cudaGetSymbolAddress((void**)&hl,    g_hl);
    cudaGetSymbolAddress((void**)&h1h,   g_h1h);
    cudaGetSymbolAddress((void**)&h1l,   g_h1l);
    cudaGetSymbolAddress((void**)&w1th,  g_w1th);
    cudaGetSymbolAddress((void**)&w1tl,  g_w1tl);
    cudaGetSymbolAddress((void**)&w2th,  g_w2th);
    cudaGetSymbolAddress((void**)&w2tl,  g_w2tl);
    cudaGetSymbolAddress((void**)&cand,  g_cand);
    cudaGetSymbolAddress((void**)&idx5,  g_idx5);
    cudaGetSymbolAddress((void**)&w5,    g_w5);

    cudaFuncSetAttribute(gemm_s, cudaFuncAttributeMaxDynamicSharedMemorySize, S_SMEM);
    cudaFuncSetAttribute(gemm_split<1>, cudaFuncAttributeMaxDynamicSharedMemorySize, MLP_SMEM);
    cudaFuncSetAttribute(gemm_split<2>, cudaFuncAttributeMaxDynamicSharedMemorySize, MLP_SMEM);

    norm_kernel<<<B_ * N_, 256>>>(x, xn, xnh);

    dim3 wt1(D_ / 32, H_ / 32), wblk(32, 8);
    wtrans_kernel<<<wt1, wblk>>>(w1, w1th, w1tl, D_);
    dim3 wt2(H_ / 32, H_ / 32);
    wtrans_kernel<<<wt2, wblk>>>(w2, w2th, w2tl, H_);

    dim3 sg(136, B_);
    gemm_s<<<sg, 256, S_SMEM>>>(xnh, candv);

    merge8_kernel<<<(B_ * N_) / 8, 256>>>(candv, cand);

    rescore_kernel<<<(B_ * N_) / 32, 256>>>(xn, cand, idx5, w5);

    agg_kernel<<<B_ * N_, 256>>>(x, idx5, w5, hh, hl);

    dim3 g1(H_ / 128, (B_ * N_) / 128);
    gemm_split<1><<<g1, 256, MLP_SMEM>>>(hh, hl, w1th, w1tl, b1,
                                         nullptr, h1h, h1l, D_);
    gemm_split<2><<<g1, 256, MLP_SMEM>>>(h1h, h1l, w2th, w2tl, b2,
                                         out, nullptr, nullptr, H_);
}